// round 2
// baseline (speedup 1.0000x reference)
#include <cuda_runtime.h>

#define TAB_N   4096
#define TAB_S   (4096.0f / 9.2f)   // index scale: u in [-4.6, 4.6] -> [0, 4096)
#define TAB_O   2048.0f

// Weight layout: [0:4) w_ih(i,f,g,o)  [4:8) w_hh  [8:12) b_ih  [12:16) b_hh
// [16:34) w_lin  [34] b_lin
__device__ float  g_w[35];
__device__ float2 g_tab[TAB_N];

__device__ __forceinline__ float tanh_fast(float x) {
    float y;
    asm("tanh.approx.f32 %0, %1;" : "=f"(y) : "f"(x));
    return y;
}
__device__ __forceinline__ float sigmoid_fast(float x) {
    return fmaf(tanh_fast(0.5f * x), 0.5f, 0.5f);
}

// Linear-interp tanh from SMEM table. Valid for any u (clamps to +/-4.6).
__device__ __forceinline__ float tanh_tab(float u, const float2* __restrict__ tab) {
    float t = fmaf(u, TAB_S, TAB_O);
    t = fminf(fmaxf(t, 0.0f), 4095.99f);
    int i = (int)t;
    float fr = t - (float)i;
    float2 e = tab[i];
    return fmaf(fr, e.y, e.x);
}

// One-block setup: gather weights + build accurate tanh table in GMEM.
__global__ void setup_kernel(const float* __restrict__ w_ih,
                             const float* __restrict__ w_hh,
                             const float* __restrict__ b_ih,
                             const float* __restrict__ b_hh,
                             const float* __restrict__ w_lin,
                             const float* __restrict__ b_lin)
{
    int t = threadIdx.x;
    if (t < 4)                 g_w[t]      = w_ih[t];
    else if (t < 8)            g_w[t]      = w_hh[t - 4];
    else if (t < 12)           g_w[t]      = b_ih[t - 8];
    else if (t < 16)           g_w[t]      = b_hh[t - 12];
    else if (t < 34)           g_w[t]      = w_lin[t - 16];
    else if (t == 34)          g_w[34]     = b_lin[0];

    const float inv_s = 1.0f / TAB_S;
    for (int i = t; i < TAB_N; i += blockDim.x) {
        float u0 = ((float)i       - TAB_O) * inv_s;
        float u1 = ((float)(i + 1) - TAB_O) * inv_s;
        float v0 = tanhf(u0);
        float v1 = tanhf(u1);
        g_tab[i] = make_float2(v0, v1 - v0);
    }
}

__global__ __launch_bounds__(512) void lstm_lin_kernel(
    const float* __restrict__ x, float* __restrict__ out, int nrows)
{
    __shared__ float2 stab[TAB_N];

    // Cooperative table copy GMEM -> SMEM (L2-resident master, cheap)
    {
        const float4* src = reinterpret_cast<const float4*>(g_tab);
        float4* dst = reinterpret_cast<float4*>(stab);
#pragma unroll
        for (int i = threadIdx.x; i < TAB_N / 2; i += 512)
            dst[i] = __ldg(src + i);
    }

    // Uniform weight loads (broadcast, L1/L2 hit)
    const float wi = __ldg(&g_w[0]), wf = __ldg(&g_w[1]),
                wg = __ldg(&g_w[2]), wo = __ldg(&g_w[3]);
    const float ui = __ldg(&g_w[4]), uf = __ldg(&g_w[5]),
                ug = __ldg(&g_w[6]), uo = __ldg(&g_w[7]);
    const float bi = __ldg(&g_w[8])  + __ldg(&g_w[12]);
    const float bf = __ldg(&g_w[9])  + __ldg(&g_w[13]);
    const float bg = __ldg(&g_w[10]) + __ldg(&g_w[14]);
    const float bo = __ldg(&g_w[11]) + __ldg(&g_w[15]);
    float wl[18];
#pragma unroll
    for (int j = 0; j < 18; j++) wl[j] = __ldg(&g_w[16 + j]);
    const float blin = __ldg(&g_w[34]);

    __syncthreads();

    const int stride = gridDim.x * 512;

    for (int r = blockIdx.x * 512 + threadIdx.x; r < nrows; r += stride) {
        const float2* p = reinterpret_cast<const float2*>(x) + (size_t)r * 9;
        float v[18];
#pragma unroll
        for (int j = 0; j < 9; j++) {
            float2 t = __ldg(p + j);
            v[2 * j] = t.x; v[2 * j + 1] = t.y;
        }

        float acc = blin;

#pragma unroll
        for (int e = 0; e < 6; e++) {
            const float x0 = v[e * 3 + 0];
            const float x1 = v[e * 3 + 1];
            const float x2 = v[e * 3 + 2];

            // step 0: h=c=0 -> forget gate dead
            float i0 = sigmoid_fast(fmaf(wi, x0, bi));
            float g0 = tanh_tab(fmaf(wg, x0, bg), stab);
            float o0 = sigmoid_fast(fmaf(wo, x0, bo));
            float c  = i0 * g0;
            float h  = o0 * tanh_tab(c, stab);
            acc = fmaf(h, wl[e * 3 + 0], acc);

            // step 1
            float i1 = sigmoid_fast(fmaf(ui, h, fmaf(wi, x1, bi)));
            float f1 = sigmoid_fast(fmaf(uf, h, fmaf(wf, x1, bf)));
            float g1 = tanh_fast  (fmaf(ug, h, fmaf(wg, x1, bg)));
            float o1 = sigmoid_fast(fmaf(uo, h, fmaf(wo, x1, bo)));
            c = fmaf(f1, c, i1 * g1);
            h = o1 * tanh_tab(c, stab);
            acc = fmaf(h, wl[e * 3 + 1], acc);

            // step 2
            float i2 = sigmoid_fast(fmaf(ui, h, fmaf(wi, x2, bi)));
            float f2 = sigmoid_fast(fmaf(uf, h, fmaf(wf, x2, bf)));
            float g2 = tanh_fast  (fmaf(ug, h, fmaf(wg, x2, bg)));
            float o2 = sigmoid_fast(fmaf(uo, h, fmaf(wo, x2, bo)));
            c = fmaf(f2, c, i2 * g2);
            h = o2 * tanh_tab(c, stab);
            acc = fmaf(h, wl[e * 3 + 2], acc);
        }

        out[r] = acc;
    }
}

extern "C" void kernel_launch(void* const* d_in, const int* in_sizes, int n_in,
                              void* d_out, int out_size)
{
    // Inputs: x, w_ih, w_hh, b_ih, b_hh, w_lin, b_lin
    const float* x = (const float*)d_in[0];

    setup_kernel<<<1, 128>>>((const float*)d_in[1], (const float*)d_in[2],
                             (const float*)d_in[3], (const float*)d_in[4],
                             (const float*)d_in[5], (const float*)d_in[6]);

    int nrows = out_size;            // 2,097,152 rows
    lstm_lin_kernel<<<592, 512>>>(x, (float*)d_out, nrows);
}

// round 3
// speedup vs baseline: 1.0759x; 1.0759x over previous
#include <cuda_runtime.h>

#define TN      2048
#define TSCALE  (TN / 9.2f)          // index scale: [-4.6,4.6] -> [0,2048)
#define TOFF    ((float)(TN / 2))
#define TINV    (9.2f / TN)

// Constant weights (prescaled): [0:4) w_ih' [4:8) w_hh' [8:12) bias'
// (i,f,o scaled by 0.5 for sigmoid folding; g unscaled)
// [12:30) w_lin  [30] b_lin
__constant__ float c_w[31];

__device__ float g_stage[31];
__device__ float g_tab[TN];

__device__ __forceinline__ float tanh_fast(float x) {
    float y;
    asm("tanh.approx.f32 %0, %1;" : "=f"(y) : "f"(x));
    return y;
}
// arg already prescaled by 0.5
__device__ __forceinline__ float sigmoid_pre(float half_x) {
    return fmaf(tanh_fast(half_x), 0.5f, 0.5f);
}

// tanh via 4B table + exact-derivative interpolation. No clamp (|u| <= 3 guaranteed).
__device__ __forceinline__ float tanh_tab(float u, const float* __restrict__ tab) {
    float t = fmaf(u, TSCALE, TOFF);
    int   i = __float2int_rn(t);
    float dx = (t - (float)i) * TINV;
    float v = tab[i];
    return fmaf(dx, fmaf(-v, v, 1.0f), v);   // v + dx*(1-v^2)
}
// clamped variant (unbounded arg)
__device__ __forceinline__ float tanh_tab_c(float u, const float* __restrict__ tab) {
    float t = fmaf(u, TSCALE, TOFF);
    t = fminf(fmaxf(t, 0.0f), (float)(TN - 1));
    int   i = __float2int_rn(t);
    float dx = (t - (float)i) * TINV;
    float v = tab[i];
    return fmaf(dx, fmaf(-v, v, 1.0f), v);
}

__global__ void setup_kernel(const float* __restrict__ w_ih,
                             const float* __restrict__ w_hh,
                             const float* __restrict__ b_ih,
                             const float* __restrict__ b_hh,
                             const float* __restrict__ w_lin,
                             const float* __restrict__ b_lin)
{
    int t = threadIdx.x;
    if (t < 4) {
        float s = (t == 2) ? 1.0f : 0.5f;          // g gate unscaled
        g_stage[t]     = w_ih[t] * s;
        g_stage[4 + t] = w_hh[t] * s;
        g_stage[8 + t] = (b_ih[t] + b_hh[t]) * s;
    } else if (t < 22) {
        g_stage[8 + t] = w_lin[t - 4];             // 12..29
    } else if (t == 22) {
        g_stage[30] = b_lin[0];
    }
    for (int i = t; i < TN; i += blockDim.x)
        g_tab[i] = tanhf(((float)i - TOFF) * TINV);
}

__global__ __launch_bounds__(256, 6) void lstm_lin_kernel(
    const float* __restrict__ x, float* __restrict__ out, int nrows)
{
    __shared__ float stab[TN];
    {
        const float4* src = reinterpret_cast<const float4*>(g_tab);
        float4* dst = reinterpret_cast<float4*>(stab);
        dst[threadIdx.x]       = __ldg(src + threadIdx.x);
        dst[threadIdx.x + 256] = __ldg(src + threadIdx.x + 256);
    }
    __syncthreads();

    const int stride = gridDim.x * 256;

    for (int r = blockIdx.x * 256 + threadIdx.x; r < nrows; r += stride) {
        const float2* p = reinterpret_cast<const float2*>(x) + (size_t)r * 9;
        float v[18];
#pragma unroll
        for (int j = 0; j < 9; j++) {
            float2 t = __ldg(p + j);
            v[2 * j] = t.x; v[2 * j + 1] = t.y;
        }

        float acc = c_w[30];

#pragma unroll
        for (int e = 0; e < 6; e++) {
            const float x0 = v[e * 3 + 0];
            const float x1 = v[e * 3 + 1];
            const float x2 = v[e * 3 + 2];

            // step 0 (h=c=0, forget gate dead)
            float i0 = sigmoid_pre(fmaf(c_w[0], x0, c_w[8]));
            float g0 = tanh_tab_c (fmaf(c_w[2], x0, c_w[10]), stab);
            float o0 = sigmoid_pre(fmaf(c_w[3], x0, c_w[11]));
            float c  = i0 * g0;
            float h  = o0 * tanh_tab(c, stab);
            acc = fmaf(h, c_w[12 + e * 3 + 0], acc);

            // step 1
            float i1 = sigmoid_pre(fmaf(c_w[4], h, fmaf(c_w[0], x1, c_w[8])));
            float f1 = sigmoid_pre(fmaf(c_w[5], h, fmaf(c_w[1], x1, c_w[9])));
            float g1 = tanh_fast  (fmaf(c_w[6], h, fmaf(c_w[2], x1, c_w[10])));
            float o1 = sigmoid_pre(fmaf(c_w[7], h, fmaf(c_w[3], x1, c_w[11])));
            c = fmaf(f1, c, i1 * g1);
            h = o1 * tanh_tab(c, stab);
            acc = fmaf(h, c_w[12 + e * 3 + 1], acc);

            // step 2
            float i2 = sigmoid_pre(fmaf(c_w[4], h, fmaf(c_w[0], x2, c_w[8])));
            float f2 = sigmoid_pre(fmaf(c_w[5], h, fmaf(c_w[1], x2, c_w[9])));
            float g2 = tanh_fast  (fmaf(c_w[6], h, fmaf(c_w[2], x2, c_w[10])));
            float o2 = sigmoid_pre(fmaf(c_w[7], h, fmaf(c_w[3], x2, c_w[11])));
            c = fmaf(f2, c, i2 * g2);
            h = o2 * tanh_tab(c, stab);
            acc = fmaf(h, c_w[12 + e * 3 + 2], acc);
        }

        out[r] = acc;
    }
}

extern "C" void kernel_launch(void* const* d_in, const int* in_sizes, int n_in,
                              void* d_out, int out_size)
{
    // Inputs: x, w_ih, w_hh, b_ih, b_hh, w_lin, b_lin
    const float* x = (const float*)d_in[0];

    setup_kernel<<<1, 256>>>((const float*)d_in[1], (const float*)d_in[2],
                             (const float*)d_in[3], (const float*)d_in[4],
                             (const float*)d_in[5], (const float*)d_in[6]);

    void* stage_ptr = nullptr;
    cudaGetSymbolAddress(&stage_ptr, g_stage);
    cudaMemcpyToSymbolAsync(c_w, stage_ptr, 31 * sizeof(float), 0,
                            cudaMemcpyDeviceToDevice, 0);

    int nrows = out_size;   // 2,097,152
    lstm_lin_kernel<<<1776, 256>>>(x, (float*)d_out, nrows);
}

// round 4
// speedup vs baseline: 1.2206x; 1.1345x over previous
#include <cuda_runtime.h>
#include <math.h>

#define TN     1024
#define TRANGE 8.0f                    // table covers x0 in [-8, 8)
#define TSCALE ((float)TN / (2.0f * TRANGE))   // 64
#define TOFFS  ((float)(TN / 2))               // 512

// Constant weights (prescaled): [0:4) w_ih' [4:8) w_hh' [8:12) bias'
// (i,f,o gates scaled by 0.5 to fold into sigmoid; g unscaled)
// [12:30) w_lin  [30] b_lin
__constant__ float c_w[31];

__device__ float  g_stage[31];
__device__ float4 g_tab[TN];   // (h0, c0, dh, dc) as function of x0

__device__ __forceinline__ float tanh_fast(float x) {
    float y;
    asm("tanh.approx.f32 %0, %1;" : "=f"(y) : "f"(x));
    return y;
}
// argument already prescaled by 0.5
__device__ __forceinline__ float sigmoid_pre(float half_x) {
    return fmaf(tanh_fast(half_x), 0.5f, 0.5f);
}

// ---------------- setup: stage weights + build exact step0 table -----------
__device__ __forceinline__ void step0_exact(
    float x, float wi, float wg, float wo, float bi, float bg, float bo,
    float* h0, float* c0)
{
    float i0 = 1.0f / (1.0f + expf(-(fmaf(wi, x, bi))));
    float g0 = tanhf(fmaf(wg, x, bg));
    float o0 = 1.0f / (1.0f + expf(-(fmaf(wo, x, bo))));
    float c  = i0 * g0;
    *c0 = c;
    *h0 = o0 * tanhf(c);
}

__global__ void setup_kernel(const float* __restrict__ w_ih,
                             const float* __restrict__ w_hh,
                             const float* __restrict__ b_ih,
                             const float* __restrict__ b_hh,
                             const float* __restrict__ w_lin,
                             const float* __restrict__ b_lin)
{
    int t = threadIdx.x;
    if (t < 4) {
        float s = (t == 2) ? 1.0f : 0.5f;       // g gate unscaled
        g_stage[t]     = w_ih[t] * s;
        g_stage[4 + t] = w_hh[t] * s;
        g_stage[8 + t] = (b_ih[t] + b_hh[t]) * s;
    } else if (t < 22) {
        g_stage[8 + t] = w_lin[t - 4];          // 12..29
    } else if (t == 22) {
        g_stage[30] = b_lin[0];
    }

    const float wi = w_ih[0], wg = w_ih[2], wo = w_ih[3];
    const float bi = b_ih[0] + b_hh[0];
    const float bg = b_ih[2] + b_hh[2];
    const float bo = b_ih[3] + b_hh[3];
    const float inv = 1.0f / TSCALE;

    for (int i = t; i < TN; i += blockDim.x) {
        float x0 = ((float)i       - TOFFS) * inv;
        float x1 = ((float)(i + 1) - TOFFS) * inv;
        float h0, c0, h1, c1;
        step0_exact(x0, wi, wg, wo, bi, bg, bo, &h0, &c0);
        step0_exact(x1, wi, wg, wo, bi, bg, bo, &h1, &c1);
        g_tab[i] = make_float4(h0, c0, h1 - h0, c1 - c0);
    }
}

// ---------------- main kernel ----------------------------------------------
__global__ __launch_bounds__(256) void lstm_lin_kernel(
    const float* __restrict__ x, float* __restrict__ out, int nrows)
{
    __shared__ float4 stab[TN];
#pragma unroll
    for (int i = threadIdx.x; i < TN; i += 256)
        stab[i] = __ldg(&g_tab[i]);
    __syncthreads();

    const int stride = gridDim.x * 256;

    for (int r = blockIdx.x * 256 + threadIdx.x; r < nrows; r += stride) {
        const float2* p = reinterpret_cast<const float2*>(x) + (size_t)r * 9;
        float v[18];
#pragma unroll
        for (int j = 0; j < 9; j++) {
            float2 t = __ldg(p + j);
            v[2 * j] = t.x; v[2 * j + 1] = t.y;
        }

        float acc = c_w[30];

#pragma unroll
        for (int e = 0; e < 6; e++) {
            const float x0 = v[e * 3 + 0];
            const float x1 = v[e * 3 + 1];
            const float x2 = v[e * 3 + 2];

            // ---- step 0: whole step is a 1-D function of x0 -> table ----
            float t = fmaf(x0, TSCALE, TOFFS);
            t = fminf(fmaxf(t, 0.0f), (float)TN - 0.51f);
            int   i  = (int)t;
            float dx = t - (float)i;
            float4 e4 = stab[i];
            float h = fmaf(dx, e4.z, e4.x);     // h0
            float c = fmaf(dx, e4.w, e4.y);     // c0
            acc = fmaf(h, c_w[12 + e * 3 + 0], acc);

            // ---- step 1 ----
            float i1 = sigmoid_pre(fmaf(c_w[4], h, fmaf(c_w[0], x1, c_w[8])));
            float f1 = sigmoid_pre(fmaf(c_w[5], h, fmaf(c_w[1], x1, c_w[9])));
            float g1 = tanh_fast  (fmaf(c_w[6], h, fmaf(c_w[2], x1, c_w[10])));
            float o1 = sigmoid_pre(fmaf(c_w[7], h, fmaf(c_w[3], x1, c_w[11])));
            c = fmaf(f1, c, i1 * g1);
            h = o1 * tanh_fast(c);
            acc = fmaf(h, c_w[12 + e * 3 + 1], acc);

            // ---- step 2 ----
            float i2 = sigmoid_pre(fmaf(c_w[4], h, fmaf(c_w[0], x2, c_w[8])));
            float f2 = sigmoid_pre(fmaf(c_w[5], h, fmaf(c_w[1], x2, c_w[9])));
            float g2 = tanh_fast  (fmaf(c_w[6], h, fmaf(c_w[2], x2, c_w[10])));
            float o2 = sigmoid_pre(fmaf(c_w[7], h, fmaf(c_w[3], x2, c_w[11])));
            c = fmaf(f2, c, i2 * g2);
            h = o2 * tanh_fast(c);
            acc = fmaf(h, c_w[12 + e * 3 + 2], acc);
        }

        out[r] = acc;
    }
}

extern "C" void kernel_launch(void* const* d_in, const int* in_sizes, int n_in,
                              void* d_out, int out_size)
{
    // Inputs: x, w_ih, w_hh, b_ih, b_hh, w_lin, b_lin
    const float* x = (const float*)d_in[0];

    setup_kernel<<<1, 256>>>((const float*)d_in[1], (const float*)d_in[2],
                             (const float*)d_in[3], (const float*)d_in[4],
                             (const float*)d_in[5], (const float*)d_in[6]);

    void* stage_ptr = nullptr;
    cudaGetSymbolAddress(&stage_ptr, g_stage);
    cudaMemcpyToSymbolAsync(c_w, stage_ptr, 31 * sizeof(float), 0,
                            cudaMemcpyDeviceToDevice, 0);

    int nrows = out_size;   // 2,097,152
    lstm_lin_kernel<<<1184, 256>>>(x, (float*)d_out, nrows);
}